// round 16
// baseline (speedup 1.0000x reference)
#include <cuda_runtime.h>
#include <math_constants.h>

// Problem constants (fixed shape)
#define BB 8
#define SS 512
#define ROWS (BB * SS)
#define VV 32000
#define V4 (VV / 4)            // 8000 float4 per row
#define EPS_SMOOTH 0.1f
#define REP_W 0.2f
#define IGNORE_IDX (-100)

#define RK_THREADS 128
#define FULL_IT (V4 / RK_THREADS)       // 62
#define REM (V4 - FULL_IT * RK_THREADS) // 64

#define GRID 1184                        // 8 blocks/SM x 148 SMs, all resident
#define NW (RK_THREADS / 32)             // 4 warps
#define SLICES 16
#define RB_BLOCKS (BB * SLICES)          // 128
#define ILOC (SS / SLICES)               // 32 i-values per rep block
#define JLEN (SS / 4)                    // 128 j per chunk-thread (4 chunks/i)

// Scratch (no allocation allowed -> __device__ globals; zero-init; counters
// reset by the final combine block each replay)
__device__ float g_per_tok[ROWS];
__device__ float g_valid[ROWS];
__device__ int   g_pred[ROWS];
__device__ float g_ent_part[RB_BLOCKS];
__device__ float g_nu_part[RB_BLOCKS];
__device__ float g_pt_part[RB_BLOCKS];
__device__ float g_v_part[RB_BLOCKS];
__device__ float g_tot_b[BB];
__device__ int   g_arrive;
__device__ int   g_arrive2;

// ---------------- packed f32x2 helpers (Blackwell) ----------------
__device__ __forceinline__ unsigned long long pack2(float a, float b) {
    unsigned long long r;
    asm("mov.b64 %0, {%1, %2};" : "=l"(r) : "f"(a), "f"(b));
    return r;
}
__device__ __forceinline__ void unpack2(unsigned long long p, float& a, float& b) {
    asm("mov.b64 {%0, %1}, %2;" : "=f"(a), "=f"(b) : "l"(p));
}
__device__ __forceinline__ unsigned long long addf2(unsigned long long a, unsigned long long b) {
    unsigned long long r;
    asm("add.rn.f32x2 %0, %1, %2;" : "=l"(r) : "l"(a), "l"(b));
    return r;
}
__device__ __forceinline__ unsigned long long mulf2(unsigned long long a, unsigned long long b) {
    unsigned long long r;
    asm("mul.rn.f32x2 %0, %1, %2;" : "=l"(r) : "l"(a), "l"(b));
    return r;
}
__device__ __forceinline__ float ex2f(float x) {
    float r;
    asm("ex2.approx.f32 %0, %1;" : "=f"(r) : "f"(x));
    return r;
}
__device__ __forceinline__ int ld_acquire(int* p) {
    int v;
    asm volatile("ld.global.acquire.gpu.b32 %0, [%1];" : "=r"(v) : "l"(p));
    return v;
}

// ---------------------------------------------------------------------------
// Persistent fused kernel at 128 threads x 8 blocks/SM: same 1024 threads/SM
// as R8/R15, but 8 independent streams per SM — per-row pipeline drains
// stagger 8-ways (R15 proved this axis: 2->4 streams gave 99.1->94.4us).
// ---------------------------------------------------------------------------
__global__ void __launch_bounds__(RK_THREADS, 8)
fused_kernel(const float* __restrict__ logits, const void* __restrict__ labels,
             float* __restrict__ out, int out_size) {
    const int tid = threadIdx.x;
    const int bid = blockIdx.x;

    __shared__ float shs[2][NW], sht[2][NW], shm[2][NW];
    __shared__ int   sha[2][NW];

    // label width detect: warp 0 only, result in registers
    int is64 = 0;
    if (tid < 32) {
        const int* lw = (const int*)labels;
        bool ok = true;
        #pragma unroll
        for (int kq = 0; kq < 8; kq++) {
            int pi = tid + kq * 32;
            int lo = __ldg(&lw[2 * pi]);
            int hi = __ldg(&lw[2 * pi + 1]);
            if (hi != (lo < 0 ? -1 : 0)) ok = false;
        }
        unsigned ball = __ballot_sync(0xffffffffu, ok);
        is64 = (ball == 0xffffffffu) ? 1 : 0;
    }

    const unsigned long long L2E2 = pack2(1.4426950408889634f, 1.4426950408889634f);

    // ---------------- Phase A: rows ----------------
    int par = 0;
    for (int row = bid; row < ROWS; row += GRID, par ^= 1) {
        const float* __restrict__ x = logits + (size_t)row * VV;
        const float4* __restrict__ x4 = (const float4*)x;

        // prefetch label -> x[label] (resolves during the row stream)
        long long lab = 0;
        float xl = 0.f;
        if (tid == 0) {
            if (is64) lab = ((const long long*)labels)[row];
            else      lab = (long long)(((const int*)labels)[row]);
            int li = (lab != IGNORE_IDX) ? (int)lab : 0;
            xl = __ldg(&x[li]);
        }

        unsigned long long s01 = 0ull, s23 = 0ull;
        unsigned long long t01 = 0ull, t23 = 0ull;
        float k0 = -CUDART_INF_F, k1 = -CUDART_INF_F, k2 = -CUDART_INF_F, k3 = -CUDART_INF_F;

        // 6-bit iteration key in the low mantissa bits (kk up to 62)
        #define BODY(kk, i)                                                         \
            do {                                                                    \
                float4 v = x4[(i)];                                                 \
                unsigned long long vxy = pack2(v.x, v.y);                           \
                unsigned long long vzw = pack2(v.z, v.w);                           \
                t01 = addf2(t01, vxy);                                              \
                t23 = addf2(t23, vzw);                                              \
                unsigned long long wxy = mulf2(vxy, L2E2);                          \
                unsigned long long wzw = mulf2(vzw, L2E2);                          \
                float w0, w1, w2, w3;                                               \
                unpack2(wxy, w0, w1);                                               \
                unpack2(wzw, w2, w3);                                               \
                float e0 = ex2f(w0), e1 = ex2f(w1), e2 = ex2f(w2), e3 = ex2f(w3);   \
                s01 = addf2(s01, pack2(e0, e1));                                    \
                s23 = addf2(s23, pack2(e2, e3));                                    \
                k0 = fmaxf(k0, __int_as_float((__float_as_int(v.x) & ~63) | (kk))); \
                k1 = fmaxf(k1, __int_as_float((__float_as_int(v.y) & ~63) | (kk))); \
                k2 = fmaxf(k2, __int_as_float((__float_as_int(v.z) & ~63) | (kk))); \
                k3 = fmaxf(k3, __int_as_float((__float_as_int(v.w) & ~63) | (kk))); \
            } while (0)

        #pragma unroll 5
        for (int k = 0; k < FULL_IT; k++) {
            BODY(k, tid + k * RK_THREADS);
        }
        if (tid < REM) {
            BODY(FULL_IT, tid + FULL_IT * RK_THREADS);
        }
        #undef BODY

        float sa, sb, sc, sd, ta, tb, tc, td;
        unpack2(s01, sa, sb);
        unpack2(s23, sc, sd);
        unpack2(t01, ta, tb);
        unpack2(t23, tc, td);
        float s = (sa + sb) + (sc + sd);
        float t = (ta + tb) + (tc + td);

        float bk = k0;
        int bs = 0;
        if (k1 > bk) { bk = k1; bs = 1; }
        if (k2 > bk) { bk = k2; bs = 2; }
        if (k3 > bk) { bk = k3; bs = 3; }
        int kb = __float_as_int(bk);
        int iter = kb & 63;
        float m = __int_as_float(kb & ~63);
        int am = (((iter * RK_THREADS) + tid) << 2) + bs;

        #pragma unroll
        for (int off = 16; off; off >>= 1) {
            float s2r = __shfl_down_sync(0xffffffffu, s, off);
            float t2r = __shfl_down_sync(0xffffffffu, t, off);
            float m2r = __shfl_down_sync(0xffffffffu, m, off);
            int   a2r = __shfl_down_sync(0xffffffffu, am, off);
            s += s2r;
            t += t2r;
            if (m2r > m || (m2r == m && a2r < am)) am = a2r;
            m = fmaxf(m, m2r);
        }

        int wid = tid >> 5;
        if ((tid & 31) == 0) { shs[par][wid] = s; sht[par][wid] = t; shm[par][wid] = m; sha[par][wid] = am; }
        __syncthreads();
        // no trailing barrier: next row uses the other parity scratch set

        if (tid < 32) {
            float es = 0.f, et = 0.f, em = -CUDART_INF_F;
            int   ea = 0x7fffffff;
            if (tid < NW) { es = shs[par][tid]; et = sht[par][tid]; em = shm[par][tid]; ea = sha[par][tid]; }
            #pragma unroll
            for (int off = NW / 2; off; off >>= 1) {
                float s2r = __shfl_down_sync(0xffffffffu, es, off);
                float t2r = __shfl_down_sync(0xffffffffu, et, off);
                float m2r = __shfl_down_sync(0xffffffffu, em, off);
                int   a2r = __shfl_down_sync(0xffffffffu, ea, off);
                es += s2r;
                et += t2r;
                if (m2r > em || (m2r == em && a2r < ea)) ea = a2r;
                em = fmaxf(em, m2r);
            }
            if (tid == 0) {
                float lse = logf(es);
                bool valid = (lab != IGNORE_IDX);
                float per = lse - (1.0f - EPS_SMOOTH) * xl - EPS_SMOOTH * (et / (float)VV);
                g_per_tok[row] = valid ? per : 0.f;
                g_valid[row]   = valid ? 1.f : 0.f;
                g_pred[row]    = ea;
            }
        }
    }

    // ---------------- grid barrier ----------------
    __threadfence();
    __syncthreads();
    if (tid == 0) atomicAdd(&g_arrive, 1);

    if (bid >= RB_BLOCKS) return;

    if (tid == 0) {
        while (ld_acquire(&g_arrive) < GRID) __nanosleep(64);
    }
    __syncthreads();
    __threadfence();

    // ---------------- Phase B: rep loss (128 threads/block, 128 blocks) ----
    const int b  = bid >> 4;        // batch
    const int sl = bid & 15;        // slice
    const int il = tid >> 2;        // i_local 0..31
    const int ch = tid & 3;         // j chunk 0..3
    const int i  = sl * ILOC + il;  // i within batch

    __shared__ int   sp[SS];
    __shared__ float sv[SS];
    __shared__ float red1[NW], red2[NW], red3[NW], red4[NW];

    {
        #pragma unroll
        for (int q = 0; q < 4; q++) {
            int idx = tid + q * RK_THREADS;
            int r0 = b * SS + idx;
            sp[idx] = g_pred[r0];
            sv[idx] = g_valid[r0];
        }
    }
    __syncthreads();

    // total valid for batch
    float total = 0.f;
    #pragma unroll
    for (int q = 0; q < 4; q++) total += sv[tid + q * RK_THREADS];
    #pragma unroll
    for (int off = 16; off; off >>= 1) total += __shfl_down_sync(0xffffffffu, total, off);
    if ((tid & 31) == 0) red1[tid >> 5] = total;
    __syncthreads();
    if (tid < 32) {
        float xx = (tid < NW) ? red1[tid] : 0.f;
        #pragma unroll
        for (int off = NW / 2; off; off >>= 1) xx += __shfl_down_sync(0xffffffffu, xx, off);
        if (tid == 0) red1[0] = xx;
    }
    __syncthreads();
    total = red1[0];
    __syncthreads();

    // per-i count + any-earlier-match; 4 chunk-threads per i, 128 j each
    int   p  = sp[i];
    float vi = sv[i];
    float c = 0.f;
    int lt = 0;
    #pragma unroll 8
    for (int jj = 0; jj < JLEN; jj++) {
        int j = ch + (jj << 2);
        bool match = (sp[j] == p) && (sv[j] > 0.f);
        c += match ? 1.f : 0.f;
        lt |= (match && (j < i)) ? 1 : 0;
    }
    #pragma unroll
    for (int off = 1; off < 4; off <<= 1) {
        c  += __shfl_xor_sync(0xffffffffu, c,  off);
        lt |= __shfl_xor_sync(0xffffffffu, lt, off);
    }

    float ent = 0.f, nu = 0.f, pts = 0.f, vls = 0.f;
    if (ch == 0) {
        bool first = (vi > 0.f) && !lt;
        if (first) {
            float pr = c / fmaxf(total, 1.f);
            ent = -pr * logf(pr + 1e-10f);
            nu  = 1.f;
        }
        int r2 = b * SS + i;
        pts = g_per_tok[r2];
        vls = vi;
    }

    #pragma unroll
    for (int off = 16; off; off >>= 1) {
        ent += __shfl_down_sync(0xffffffffu, ent, off);
        nu  += __shfl_down_sync(0xffffffffu, nu,  off);
        pts += __shfl_down_sync(0xffffffffu, pts, off);
        vls += __shfl_down_sync(0xffffffffu, vls, off);
    }
    if ((tid & 31) == 0) { red1[tid >> 5] = ent; red2[tid >> 5] = nu; red3[tid >> 5] = pts; red4[tid >> 5] = vls; }
    __syncthreads();
    if (tid < 32) {
        float e = (tid < NW) ? red1[tid] : 0.f;
        float n = (tid < NW) ? red2[tid] : 0.f;
        float q = (tid < NW) ? red3[tid] : 0.f;
        float w = (tid < NW) ? red4[tid] : 0.f;
        #pragma unroll
        for (int off = NW / 2; off; off >>= 1) {
            e += __shfl_down_sync(0xffffffffu, e, off);
            n += __shfl_down_sync(0xffffffffu, n, off);
            q += __shfl_down_sync(0xffffffffu, q, off);
            w += __shfl_down_sync(0xffffffffu, w, off);
        }
        if (tid == 0) {
            g_ent_part[bid] = e;
            g_nu_part[bid]  = n;
            g_pt_part[bid]  = q;
            g_v_part[bid]   = w;
            if (sl == 0) g_tot_b[b] = total;
        }
    }
    __syncthreads();

    if (tid == 0) {
        __threadfence();
        int old = atomicAdd(&g_arrive2, 1);
        if (old == RB_BLOCKS - 1) {
            __threadfence();
            float rep = 0.f;
            #pragma unroll
            for (int bb = 0; bb < BB; bb++) {
                float eb = 0.f, nb = 0.f;
                #pragma unroll
                for (int ss2 = 0; ss2 < SLICES; ss2++) {
                    eb += g_ent_part[bb * SLICES + ss2];
                    nb += g_nu_part[bb * SLICES + ss2];
                }
                float tb2 = g_tot_b[bb];
                rep += (tb2 > 0.f) ? (1.f - eb / logf(nb + 1.f)) : 0.f;
            }
            rep /= (float)BB;
            float cen = 0.f, ced = 0.f;
            #pragma unroll
            for (int jq = 0; jq < RB_BLOCKS; jq++) {
                cen += g_pt_part[jq];
                ced += g_v_part[jq];
            }
            float ce = cen / fmaxf(ced, 1.f);
            float tot = ce + REP_W * rep;
            out[0] = tot;
            if (out_size > 1) out[1] = ce;
            if (out_size > 2) out[2] = rep;
            g_arrive  = 0;   // replay-safe resets (all spins already passed)
            g_arrive2 = 0;
        }
    }
}

extern "C" void kernel_launch(void* const* d_in, const int* in_sizes, int n_in,
                              void* d_out, int out_size) {
    const float* logits = (const float*)d_in[0];
    const void*  labels = d_in[1];

    fused_kernel<<<GRID, RK_THREADS>>>(logits, labels, (float*)d_out, out_size);
}